// round 7
// baseline (speedup 1.0000x reference)
#include <cuda_runtime.h>

// MedianBlur: out = x + 0.2*(median3x3(x, zero-pad) - x)
// x: (8, 64, 256, 256) fp32 -> 512 independent 256x256 images.
// 1 warp-task = 8-row x 256-col band; lane owns 8 cols (two float4s).
// Horizontal halo via 2 shuffles/row; vertical via rolling registers with a
// one-row raw prefetch. Persistent warps pull band-tasks from a global
// atomic queue (next task prefetched while current band computes) to
// eliminate wave-quantization idle.

#define H 256
#define W 256
#define RPW 8
#define RES_SCALE 0.2f
#define NTASKS (512 * 32)      // 512 images x 32 bands

__device__ unsigned int g_task_ctr;

struct Raw { float4 a, b; };

__device__ __forceinline__ Raw load_raw(const float* __restrict__ img,
                                        int g, int lane) {
    Raw r;
    if (g >= 0 && g < H) {
        const float4* p = reinterpret_cast<const float4*>(img + g * W);
        r.a = p[lane * 2];
        r.b = p[lane * 2 + 1];
    } else {
        r.a = make_float4(0.f, 0.f, 0.f, 0.f);
        r.b = r.a;
    }
    return r;
}

__device__ __forceinline__ void finish_row(const Raw& p, int lane, float r[10]) {
    r[1] = p.a.x; r[2] = p.a.y; r[3] = p.a.z; r[4] = p.a.w;
    r[5] = p.b.x; r[6] = p.b.y; r[7] = p.b.z; r[8] = p.b.w;
    float lf = __shfl_up_sync(0xffffffffu, p.b.w, 1);
    float rt = __shfl_down_sync(0xffffffffu, p.a.x, 1);
    r[0] = (lane == 0)  ? 0.f : lf;
    r[9] = (lane == 31) ? 0.f : rt;
}

__device__ __forceinline__ void sort3(float x0, float x1, float x2,
                                      float& mn, float& md, float& mx) {
    float lo = fminf(x0, x1);
    float hi = fmaxf(x0, x1);
    mn = fminf(lo, x2);
    md = fminf(fmaxf(x2, lo), hi);
    mx = fmaxf(hi, x2);
}

__device__ __forceinline__ float med3(float a, float b, float c) {
    float lo = fminf(a, b), hi = fmaxf(a, b);
    return fminf(fmaxf(c, lo), hi);
}

__device__ __forceinline__ void do_band(const float* __restrict__ x,
                                        float* __restrict__ out,
                                        int task, int lane) {
    const int n    = task >> 5;
    const int band = task & 31;
    const float* img = x   + (size_t)n * H * W;
    float*       o   = out + (size_t)n * H * W;
    const int y0 = band * RPW;

    float r0[10], r1[10], r2[10];
    {
        Raw t0 = load_raw(img, y0 - 1, lane);
        Raw t1 = load_raw(img, y0,     lane);
        finish_row(t0, lane, r0);
        finish_row(t1, lane, r1);
    }
    Raw pre = load_raw(img, y0 + 1, lane);

    #pragma unroll
    for (int i = 0; i < RPW; ++i) {
        const int y = y0 + i;

        finish_row(pre, lane, r2);
        pre = load_raw(img, y + 2, lane);   // next row, OOB -> zeros

        float mn0, md0, mx0, mn1, md1, mx1, mn2, md2, mx2;
        sort3(r0[0], r1[0], r2[0], mn0, md0, mx0);
        sort3(r0[1], r1[1], r2[1], mn1, md1, mx1);

        float res[8];
        #pragma unroll
        for (int j = 0; j < 8; ++j) {
            sort3(r0[j + 2], r1[j + 2], r2[j + 2], mn2, md2, mx2);
            float A = fmaxf(fmaxf(mn0, mn1), mn2);
            float C = fminf(fminf(mx0, mx1), mx2);
            float B = med3(md0, md1, md2);
            float med = med3(A, B, C);
            float xc = r1[j + 1];
            res[j] = fmaf(RES_SCALE, med - xc, xc);
            mn0 = mn1; md0 = md1; mx0 = mx1;
            mn1 = mn2; md1 = md2; mx1 = mx2;
        }

        float4* op = reinterpret_cast<float4*>(o + y * W) + lane * 2;
        op[0] = make_float4(res[0], res[1], res[2], res[3]);
        op[1] = make_float4(res[4], res[5], res[6], res[7]);

        #pragma unroll
        for (int j = 0; j < 10; ++j) { r0[j] = r1[j]; r1[j] = r2[j]; }
    }
}

__global__ void zero_ctr_kernel() { g_task_ctr = 0u; }

__global__ void __launch_bounds__(256, 4)
median_blur_kernel(const float* __restrict__ x, float* __restrict__ out) {
    const int lane = threadIdx.x & 31;

    // fetch first task
    unsigned int t;
    if (lane == 0) t = atomicAdd(&g_task_ctr, 1u);
    t = __shfl_sync(0xffffffffu, t, 0);

    while (t < NTASKS) {
        // prefetch next task index; ATOMG latency overlaps band compute
        unsigned int nt;
        if (lane == 0) nt = atomicAdd(&g_task_ctr, 1u);

        do_band(x, out, (int)t, lane);

        nt = __shfl_sync(0xffffffffu, nt, 0);
        t = nt;
    }
}

extern "C" void kernel_launch(void* const* d_in, const int* in_sizes, int n_in,
                              void* d_out, int out_size) {
    const float* x = (const float*)d_in[0];
    float* out = (float*)d_out;
    zero_ctr_kernel<<<1, 1>>>();
    // persistent: 4 blocks/SM x 148 SMs = 592 blocks, 4736 warps
    median_blur_kernel<<<592, 256>>>(x, out);
}

// round 8
// speedup vs baseline: 1.1250x; 1.1250x over previous
#include <cuda_runtime.h>

// MedianBlur: out = x + 0.2*(median3x3(x, zero-pad) - x)
// x: (8, 64, 256, 256) fp32 -> 512 independent 256x256 images.
// Warp = 8-row x 256-col band; lane owns 8 cols. TWO output rows per
// iteration: column sort3s for rows (y-1,y,y+1) and (y,y+1,y+2) share the
// sorted pair of (y,y+1)  [12 -> 10 ops/col/2rows].  Horizontal merge
// processes pixels in pairs sharing the middle-column component pairs
// [14 -> 12 ops/px].  All min/max exact -> bitwise-identical median.

#define H 256
#define W 256
#define RES_SCALE 0.2f

struct Raw { float4 a, b; };

__device__ __forceinline__ Raw load_raw(const float* __restrict__ img,
                                        int g, int lane) {
    Raw r;
    if (g >= 0 && g < H) {
        const float4* p = reinterpret_cast<const float4*>(img + g * W);
        r.a = p[lane * 2];
        r.b = p[lane * 2 + 1];
    } else {
        r.a = make_float4(0.f, 0.f, 0.f, 0.f);
        r.b = r.a;
    }
    return r;
}

__device__ __forceinline__ void finish_row(const Raw& p, int lane, float r[10]) {
    r[1] = p.a.x; r[2] = p.a.y; r[3] = p.a.z; r[4] = p.a.w;
    r[5] = p.b.x; r[6] = p.b.y; r[7] = p.b.z; r[8] = p.b.w;
    float lf = __shfl_up_sync(0xffffffffu, p.b.w, 1);
    float rt = __shfl_down_sync(0xffffffffu, p.a.x, 1);
    r[0] = (lane == 0)  ? 0.f : lf;
    r[9] = (lane == 31) ? 0.f : rt;
}

// two vertical sort3s sharing the sorted pair of (x1,x2):
//  triple A = sort3(x0,x1,x2), triple B = sort3(x1,x2,x3)
__device__ __forceinline__ void colsort2(float x0, float x1, float x2, float x3,
                                         float& mnA, float& mdA, float& mxA,
                                         float& mnB, float& mdB, float& mxB) {
    float pn = fminf(x1, x2);
    float px = fmaxf(x1, x2);
    mnA = fminf(x0, pn);
    float ta = fmaxf(x0, pn);
    mdA = fminf(ta, px);
    mxA = fmaxf(x0, px);
    mnB = fminf(x3, pn);
    float tb = fmaxf(x3, pn);
    mdB = fminf(tb, px);
    mxB = fmaxf(x3, px);
}

__device__ __forceinline__ float med3(float a, float b, float c) {
    float lo = fminf(a, b), hi = fmaxf(a, b);
    return fminf(fmaxf(c, lo), hi);
}

__global__ void __launch_bounds__(256, 3)
median_blur_kernel(const float* __restrict__ x, float* __restrict__ out) {
    const int lane = threadIdx.x & 31;
    const int wg   = blockIdx.x * (blockDim.x >> 5) + (threadIdx.x >> 5);
    const int n    = wg >> 5;            // image (32 bands per image)
    const int band = wg & 31;
    const int y0   = band * 8;
    const int xc0  = lane * 8;

    const float* img = x   + (size_t)n * H * W;
    float*       o   = out + (size_t)n * H * W;

    float r0[10], r1[10], r2[10], r3[10];
    { Raw t = load_raw(img, y0 - 1, lane); finish_row(t, lane, r0); }
    { Raw t = load_raw(img, y0,     lane); finish_row(t, lane, r1); }

    #pragma unroll
    for (int i = 0; i < 4; ++i) {
        const int y = y0 + 2 * i;
        {
            Raw ta = load_raw(img, y + 1, lane);
            Raw tb = load_raw(img, y + 2, lane);   // OOB -> zeros
            finish_row(ta, lane, r2);
            finish_row(tb, lane, r3);
        }

        // sliding 4-column triple window (cols c..c+3), both row-triples
        float mnA[4], mdA[4], mxA[4], mnB[4], mdB[4], mxB[4];
        colsort2(r0[0], r1[0], r2[0], r3[0],
                 mnA[0], mdA[0], mxA[0], mnB[0], mdB[0], mxB[0]);
        colsort2(r0[1], r1[1], r2[1], r3[1],
                 mnA[1], mdA[1], mxA[1], mnB[1], mdB[1], mxB[1]);

        float resA[4], resB[4];
        #pragma unroll
        for (int k = 0; k < 4; ++k) {
            const int c2 = 2 * k + 2, c3 = 2 * k + 3;
            colsort2(r0[c2], r1[c2], r2[c2], r3[c2],
                     mnA[2], mdA[2], mxA[2], mnB[2], mdB[2], mxB[2]);
            colsort2(r0[c3], r1[c3], r2[c3], r3[c3],
                     mnA[3], mdA[3], mxA[3], mnB[3], mdB[3], mxB[3]);

            const int s = (2 * k) & 3;           // res slot (0 or 2)

            // ---- output row y (triples A); pixels 2k and 2k+1 ----
            {
                float p  = fmaxf(mnA[1], mnA[2]);
                float A0 = fmaxf(mnA[0], p);
                float A1 = fmaxf(p, mnA[3]);
                float q  = fminf(mxA[1], mxA[2]);
                float C0 = fminf(mxA[0], q);
                float C1 = fminf(q, mxA[3]);
                float lo = fminf(mdA[1], mdA[2]);
                float hi = fmaxf(mdA[1], mdA[2]);
                float B0 = fminf(fmaxf(mdA[0], lo), hi);
                float B1 = fminf(fmaxf(mdA[3], lo), hi);
                float M0 = med3(A0, B0, C0);
                float M1 = med3(A1, B1, C1);
                float xa = r1[2 * k + 1], xb = r1[2 * k + 2];
                resA[s]     = fmaf(RES_SCALE, M0 - xa, xa);
                resA[s + 1] = fmaf(RES_SCALE, M1 - xb, xb);
            }
            // ---- output row y+1 (triples B) ----
            {
                float p  = fmaxf(mnB[1], mnB[2]);
                float A0 = fmaxf(mnB[0], p);
                float A1 = fmaxf(p, mnB[3]);
                float q  = fminf(mxB[1], mxB[2]);
                float C0 = fminf(mxB[0], q);
                float C1 = fminf(q, mxB[3]);
                float lo = fminf(mdB[1], mdB[2]);
                float hi = fmaxf(mdB[1], mdB[2]);
                float B0 = fminf(fmaxf(mdB[0], lo), hi);
                float B1 = fminf(fmaxf(mdB[3], lo), hi);
                float M0 = med3(A0, B0, C0);
                float M1 = med3(A1, B1, C1);
                float xa = r2[2 * k + 1], xb = r2[2 * k + 2];
                resB[s]     = fmaf(RES_SCALE, M0 - xa, xa);
                resB[s + 1] = fmaf(RES_SCALE, M1 - xb, xb);
            }

            if (k == 1 || k == 3) {              // 4 pixels ready per row
                const int xo = xc0 + (k == 1 ? 0 : 4);
                *reinterpret_cast<float4*>(o + (size_t)(y    ) * W + xo) =
                    make_float4(resA[0], resA[1], resA[2], resA[3]);
                *reinterpret_cast<float4*>(o + (size_t)(y + 1) * W + xo) =
                    make_float4(resB[0], resB[1], resB[2], resB[3]);
            }

            // shift triple window by 2 columns
            #pragma unroll
            for (int t = 0; t < 2; ++t) {
                mnA[t] = mnA[t + 2]; mdA[t] = mdA[t + 2]; mxA[t] = mxA[t + 2];
                mnB[t] = mnB[t + 2]; mdB[t] = mdB[t + 2]; mxB[t] = mxB[t + 2];
            }
        }

        // roll two rows down: (y+1, y+2) become (y'-1, y')
        #pragma unroll
        for (int j = 0; j < 10; ++j) { r0[j] = r2[j]; r1[j] = r3[j]; }
    }
}

extern "C" void kernel_launch(void* const* d_in, const int* in_sizes, int n_in,
                              void* d_out, int out_size) {
    const float* x = (const float*)d_in[0];
    float* out = (float*)d_out;
    // 512 images * 32 bands = 16384 warp-tasks; 8 warps/block -> 2048 blocks
    median_blur_kernel<<<2048, 256>>>(x, out);
}